// round 2
// baseline (speedup 1.0000x reference)
#include <cuda_runtime.h>
#include <cuda_bf16.h>
#include <math.h>

#define NN   100000
#define EE   1600000
#define ET   1700000      // EE + NN self loops
#define FIN  512
#define HD   64           // H1*D1
#define H1   8
#define D1   8
#define CC   16

// ---------------- scratch (static device memory; no allocations) ----------------
__device__ int   g_flag;                 // 1 if edge_index is int64
__device__ int   g_src[ET];
__device__ int   g_dst[ET];
__device__ int   g_col[ET];              // CSR column (src) sorted by dst
__device__ int   g_counts[NN];
__device__ int   g_cursor[NN];
__device__ int   g_rowptr[NN + 1];
__device__ float g_h1[(size_t)NN * HD];
__device__ float g_h1act[(size_t)NN * HD];
__device__ float g_es1[(size_t)NN * H1];
__device__ float g_ed1[(size_t)NN * H1];
__device__ float g_h2[(size_t)NN * CC];
__device__ float g_es2[NN];
__device__ float g_ed2[NN];

// ---------------- dtype detection for edge_index (int64 vs int32) ----------------
__global__ __launch_bounds__(32) void detect_kernel(const int* ei32) {
    if (threadIdx.x == 0 && blockIdx.x == 0) {
        int is64 = 1;
        for (int j = 0; j < 256; j++) {
            int k = j * 6250;              // k < EE, so 2k+1 < 2*EE (safe for int32 buffer too)
            if (ei32[2 * k + 1] != 0) { is64 = 0; break; }
        }
        g_flag = is64;
    }
}

__global__ __launch_bounds__(256) void convert_kernel(const void* ei) {
    int e = blockIdx.x * blockDim.x + threadIdx.x;
    if (e >= ET) return;
    if (e < EE) {
        int s, d;
        if (g_flag) {
            const long long* p = (const long long*)ei;
            s = (int)p[e]; d = (int)p[EE + e];
        } else {
            const int* p = (const int*)ei;
            s = p[e]; d = p[EE + e];
        }
        g_src[e] = s; g_dst[e] = d;
    } else {
        g_src[e] = e - EE; g_dst[e] = e - EE;   // self loops
    }
}

// ---------------- CSR build ----------------
__global__ __launch_bounds__(256) void zero_counts_kernel() {
    int i = blockIdx.x * blockDim.x + threadIdx.x;
    if (i < NN) g_counts[i] = 0;
}

__global__ __launch_bounds__(256) void hist_kernel() {
    int e = blockIdx.x * blockDim.x + threadIdx.x;
    if (e < ET) atomicAdd(&g_counts[g_dst[e]], 1);
}

__global__ __launch_bounds__(256) void scan_kernel() {
    __shared__ int sums[256];
    int t = threadIdx.x;
    const int CH = (NN + 255) / 256;       // 391
    int base = t * CH;
    int s = 0;
    for (int i = 0; i < CH; i++) {
        int idx = base + i;
        if (idx < NN) s += g_counts[idx];
    }
    sums[t] = s;
    __syncthreads();
    // Hillis-Steele inclusive scan
    for (int off = 1; off < 256; off <<= 1) {
        int v = (t >= off) ? sums[t - off] : 0;
        __syncthreads();
        sums[t] += v;
        __syncthreads();
    }
    int run = (t == 0) ? 0 : sums[t - 1];
    for (int i = 0; i < CH; i++) {
        int idx = base + i;
        if (idx < NN) { g_rowptr[idx] = run; run += g_counts[idx]; }
    }
    if (t == 0) g_rowptr[NN] = ET;
}

__global__ __launch_bounds__(256) void cursor_kernel() {
    int i = blockIdx.x * blockDim.x + threadIdx.x;
    if (i < NN) g_cursor[i] = g_rowptr[i];
}

__global__ __launch_bounds__(256) void scatter_kernel() {
    int e = blockIdx.x * blockDim.x + threadIdx.x;
    if (e < ET) {
        int d = g_dst[e];
        int pos = atomicAdd(&g_cursor[d], 1);
        g_col[pos] = g_src[e];
    }
}

// ---------------- GEMM1: h1 = x @ W1 (100000x512 @ 512x64) ----------------
#define BM 128
#define BN 64
#define BK 16
__global__ __launch_bounds__(256) void gemm1_kernel(const float* __restrict__ x,
                                                    const float* __restrict__ W) {
    __shared__ float As[BK][BM];   // transposed x tile
    __shared__ float Bs[BK][BN];
    int block_row = blockIdx.x * BM;
    int tid = threadIdx.x;          // 256
    int tx = tid & 15;              // col group (4 cols each)
    int ty = tid >> 4;              // row group (8 rows each)
    int lr = tid >> 2;              // 0..63 : x load row
    int lc = (tid & 3) * 4;         // 0,4,8,12 : x load col
    int wr = tid >> 4;              // W load row 0..15
    int wc = (tid & 15) * 4;        // W load col

    float acc[8][4];
    #pragma unroll
    for (int i = 0; i < 8; i++)
        #pragma unroll
        for (int j = 0; j < 4; j++) acc[i][j] = 0.f;

    for (int k0 = 0; k0 < FIN; k0 += BK) {
        #pragma unroll
        for (int h = 0; h < 2; h++) {
            int r = lr + h * 64;
            int gr = block_row + r;
            float4 v = make_float4(0.f, 0.f, 0.f, 0.f);
            if (gr < NN) v = *(const float4*)(x + (size_t)gr * FIN + k0 + lc);
            As[lc + 0][r] = v.x; As[lc + 1][r] = v.y;
            As[lc + 2][r] = v.z; As[lc + 3][r] = v.w;
        }
        {
            float4 wv = *(const float4*)(W + (size_t)(k0 + wr) * BN + wc);
            Bs[wr][wc + 0] = wv.x; Bs[wr][wc + 1] = wv.y;
            Bs[wr][wc + 2] = wv.z; Bs[wr][wc + 3] = wv.w;
        }
        __syncthreads();
        #pragma unroll
        for (int k = 0; k < BK; k++) {
            float a[8], b[4];
            #pragma unroll
            for (int i = 0; i < 8; i++) a[i] = As[k][ty * 8 + i];
            #pragma unroll
            for (int j = 0; j < 4; j++) b[j] = Bs[k][tx * 4 + j];
            #pragma unroll
            for (int i = 0; i < 8; i++)
                #pragma unroll
                for (int j = 0; j < 4; j++) acc[i][j] += a[i] * b[j];
        }
        __syncthreads();
    }
    #pragma unroll
    for (int i = 0; i < 8; i++) {
        int gr = block_row + ty * 8 + i;
        if (gr < NN) {
            float4 v = make_float4(acc[i][0], acc[i][1], acc[i][2], acc[i][3]);
            *(float4*)(g_h1 + (size_t)gr * HD + tx * 4) = v;
        }
    }
}

// ---------------- attention scalars layer 1 ----------------
__global__ __launch_bounds__(256) void esed1_kernel(const float* __restrict__ a1s,
                                                    const float* __restrict__ a1d) {
    int idx = blockIdx.x * blockDim.x + threadIdx.x;
    if (idx >= NN * H1) return;
    int n = idx >> 3, h = idx & 7;
    const float* hp = g_h1 + (size_t)n * HD + h * D1;
    float s = 0.f, d = 0.f;
    #pragma unroll
    for (int j = 0; j < D1; j++) {
        float v = hp[j];
        s += v * a1s[h * D1 + j];
        d += v * a1d[h * D1 + j];
    }
    g_es1[idx] = s;
    g_ed1[idx] = d;
}

// ---------------- layer-1 aggregation: warp per dst, online softmax, ELU ----------------
__global__ __launch_bounds__(256) void agg1_kernel() {
    int warp = (blockIdx.x * blockDim.x + threadIdx.x) >> 5;
    int lane = threadIdx.x & 31;
    if (warp >= NN) return;
    int dst = warp;
    int head0 = lane >> 3;                 // head of dim d0 = lane
    float edv = (lane < 8) ? g_ed1[(size_t)dst * H1 + lane] : 0.f;
    float m = -INFINITY, s = 0.f;
    float acc0 = 0.f, acc1 = 0.f;
    int beg = g_rowptr[dst], end = g_rowptr[dst + 1];
    for (int e = beg; e < end; e++) {
        int src = g_col[e];
        float scale = 1.f, w = 0.f;
        if (lane < 8) {
            float ev = g_es1[(size_t)src * H1 + lane] + edv;
            ev = ev > 0.f ? ev : 0.2f * ev;
            float nm = fmaxf(m, ev);
            scale = __expf(m - nm);
            w = __expf(ev - nm);
            m = nm;
            s = s * scale + w;
        }
        float sc0 = __shfl_sync(0xffffffffu, scale, head0);
        float w0  = __shfl_sync(0xffffffffu, w,     head0);
        float sc1 = __shfl_sync(0xffffffffu, scale, head0 + 4);
        float w1  = __shfl_sync(0xffffffffu, w,     head0 + 4);
        float hv0 = g_h1[(size_t)src * HD + lane];
        float hv1 = g_h1[(size_t)src * HD + lane + 32];
        acc0 = acc0 * sc0 + hv0 * w0;
        acc1 = acc1 * sc1 + hv1 * w1;
    }
    float s0 = __shfl_sync(0xffffffffu, s, head0);
    float s1 = __shfl_sync(0xffffffffu, s, head0 + 4);
    float o0 = acc0 / s0;
    float o1 = acc1 / s1;
    o0 = o0 > 0.f ? o0 : expm1f(o0);       // ELU
    o1 = o1 > 0.f ? o1 : expm1f(o1);
    g_h1act[(size_t)dst * HD + lane] = o0;
    g_h1act[(size_t)dst * HD + lane + 32] = o1;
}

// ---------------- GEMM2: h2 = h1act @ W2 (64 -> 16) ----------------
__global__ __launch_bounds__(256) void gemm2_kernel(const float* __restrict__ W2) {
    __shared__ float Ws[HD * CC];
    int t = threadIdx.x;
    {
        float4 v = ((const float4*)W2)[t];   // 1024 floats = 256 float4
        ((float4*)Ws)[t] = v;
    }
    __syncthreads();
    int idx = blockIdx.x * 256 + t;
    if (idx >= NN * CC) return;
    int n = idx >> 4, c = idx & 15;
    const float4* h4 = (const float4*)(g_h1act + (size_t)n * HD);
    float sum = 0.f;
    #pragma unroll
    for (int j = 0; j < 16; j++) {
        float4 v = h4[j];
        sum += v.x * Ws[(4 * j + 0) * CC + c];
        sum += v.y * Ws[(4 * j + 1) * CC + c];
        sum += v.z * Ws[(4 * j + 2) * CC + c];
        sum += v.w * Ws[(4 * j + 3) * CC + c];
    }
    g_h2[idx] = sum;
}

__global__ __launch_bounds__(256) void esed2_kernel(const float* __restrict__ a2s,
                                                    const float* __restrict__ a2d) {
    int n = blockIdx.x * blockDim.x + threadIdx.x;
    if (n >= NN) return;
    const float4* h4 = (const float4*)(g_h2 + (size_t)n * CC);
    float s = 0.f, d = 0.f;
    #pragma unroll
    for (int j = 0; j < 4; j++) {
        float4 v = h4[j];
        s += v.x * a2s[4 * j + 0] + v.y * a2s[4 * j + 1] + v.z * a2s[4 * j + 2] + v.w * a2s[4 * j + 3];
        d += v.x * a2d[4 * j + 0] + v.y * a2d[4 * j + 1] + v.z * a2d[4 * j + 2] + v.w * a2d[4 * j + 3];
    }
    g_es2[n] = s;
    g_ed2[n] = d;
}

// ---------------- layer-2 aggregation + log_softmax : half-warp per dst ----------------
__global__ __launch_bounds__(256) void agg2_kernel(float* __restrict__ out) {
    int gw = (blockIdx.x * blockDim.x + threadIdx.x) >> 5;
    int lane = threadIdx.x & 31;
    int half = lane >> 4;
    int r = lane & 15;
    int dst = gw * 2 + half;     // NN even and grid exact -> always valid
    float edv = g_ed2[dst];
    float m = -INFINITY, s = 0.f, acc = 0.f;
    int beg = g_rowptr[dst], end = g_rowptr[dst + 1];
    for (int e = beg; e < end; e++) {
        int src = g_col[e];
        float ev = g_es2[src] + edv;
        ev = ev > 0.f ? ev : 0.2f * ev;
        float nm = fmaxf(m, ev);
        float scale = __expf(m - nm);
        float w = __expf(ev - nm);
        m = nm;
        s = s * scale + w;
        acc = acc * scale + g_h2[(size_t)src * CC + r] * w;
    }
    float o = acc / s;
    // log_softmax over 16 classes within half-warp
    float mx = o;
    #pragma unroll
    for (int off = 8; off; off >>= 1)
        mx = fmaxf(mx, __shfl_xor_sync(0xffffffffu, mx, off, 16));
    float se = __expf(o - mx);
    #pragma unroll
    for (int off = 8; off; off >>= 1)
        se += __shfl_xor_sync(0xffffffffu, se, off, 16);
    out[(size_t)dst * CC + r] = o - mx - logf(se);
}

// ---------------- launch ----------------
extern "C" void kernel_launch(void* const* d_in, const int* in_sizes, int n_in,
                              void* d_out, int out_size) {
    const float* x    = (const float*)d_in[0];
    const void*  ei   = d_in[1];
    const float* W1   = (const float*)d_in[2];
    const float* a1s  = (const float*)d_in[3];
    const float* a1d  = (const float*)d_in[4];
    const float* W2   = (const float*)d_in[5];
    const float* a2s  = (const float*)d_in[6];
    const float* a2d  = (const float*)d_in[7];
    float* out = (float*)d_out;

    detect_kernel<<<1, 32>>>((const int*)ei);
    convert_kernel<<<(ET + 255) / 256, 256>>>(ei);
    zero_counts_kernel<<<(NN + 255) / 256, 256>>>();
    hist_kernel<<<(ET + 255) / 256, 256>>>();
    scan_kernel<<<1, 256>>>();
    cursor_kernel<<<(NN + 255) / 256, 256>>>();
    scatter_kernel<<<(ET + 255) / 256, 256>>>();

    gemm1_kernel<<<(NN + BM - 1) / BM, 256>>>(x, W1);
    esed1_kernel<<<(NN * H1 + 255) / 256, 256>>>(a1s, a1d);
    agg1_kernel<<<(NN * 32 + 255) / 256, 256>>>();

    gemm2_kernel<<<(NN * CC + 255) / 256, 256>>>(W2);
    esed2_kernel<<<(NN + 255) / 256, 256>>>(a2s, a2d);
    agg2_kernel<<<(NN * 16 + 255) / 256, 256>>>(out);
}

// round 3
// speedup vs baseline: 1.5193x; 1.5193x over previous
#include <cuda_runtime.h>
#include <cuda_bf16.h>
#include <math.h>

#define NN   100000
#define EE   1600000
#define ET   1700000      // EE + NN self loops
#define FIN  512
#define HD   64           // H1*D1
#define H1   8
#define D1   8
#define CC   16

// ---------------- scratch (static device memory; no allocations) ----------------
__device__ int   g_flag;                 // 1 if edge_index is int64
__device__ int   g_src[ET];
__device__ int   g_dst[ET];
__device__ int   g_col[ET];              // CSR column (src) sorted by dst
__device__ int   g_counts[NN];
__device__ int   g_cursor[NN];
__device__ int   g_rowptr[NN + 1];
__device__ float g_h1[(size_t)NN * HD];
__device__ float g_h1act[(size_t)NN * HD];
__device__ float g_es1[(size_t)NN * H1];
__device__ float g_ed1[(size_t)NN * H1];
__device__ float g_h2[(size_t)NN * CC];
__device__ float g_es2[NN];
__device__ float g_ed2[NN];

// ---------------- init: zero counts + parallel dtype detection ----------------
__global__ __launch_bounds__(256) void init_kernel(const int* ei32) {
    int i = blockIdx.x * blockDim.x + threadIdx.x;
    if (i < NN) g_counts[i] = 0;
    if (blockIdx.x == 0 && threadIdx.x < 32) {
        int lane = threadIdx.x;
        int bad = 0;
        // 256 samples spread over EE; for int64 input the high words are 0.
        for (int j = lane; j < 256; j += 32) {
            int k = j * 6250;               // < EE, so 2k+1 < 2*EE (safe for int32 too)
            if (ei32[2 * k + 1] != 0) bad = 1;
        }
        unsigned b = __ballot_sync(0xffffffffu, bad);
        if (lane == 0) g_flag = (b == 0) ? 1 : 0;
    }
}

// ---------------- convert + histogram in one edge pass ----------------
__global__ __launch_bounds__(256) void convert_hist_kernel(const void* ei) {
    int e = blockIdx.x * blockDim.x + threadIdx.x;
    if (e >= ET) return;
    int s, d;
    if (e < EE) {
        if (g_flag) {
            const long long* p = (const long long*)ei;
            s = (int)p[e]; d = (int)p[EE + e];
        } else {
            const int* p = (const int*)ei;
            s = p[e]; d = p[EE + e];
        }
    } else {
        s = e - EE; d = e - EE;             // self loops
    }
    g_src[e] = s; g_dst[e] = d;
    atomicAdd(&g_counts[d], 1);
}

// ---------------- scan: rowptr + cursor ----------------
__global__ __launch_bounds__(512) void scan_kernel() {
    __shared__ int sums[512];
    int t = threadIdx.x;
    const int CH = (NN + 511) / 512;        // 196
    int base = t * CH;
    int s = 0;
    for (int i = 0; i < CH; i++) {
        int idx = base + i;
        if (idx < NN) s += g_counts[idx];
    }
    sums[t] = s;
    __syncthreads();
    for (int off = 1; off < 512; off <<= 1) {
        int v = (t >= off) ? sums[t - off] : 0;
        __syncthreads();
        sums[t] += v;
        __syncthreads();
    }
    int run = (t == 0) ? 0 : sums[t - 1];
    for (int i = 0; i < CH; i++) {
        int idx = base + i;
        if (idx < NN) {
            g_rowptr[idx] = run;
            g_cursor[idx] = run;
            run += g_counts[idx];
        }
    }
    if (t == 0) g_rowptr[NN] = ET;
}

__global__ __launch_bounds__(256) void scatter_kernel() {
    int e = blockIdx.x * blockDim.x + threadIdx.x;
    if (e < ET) {
        int d = g_dst[e];
        int pos = atomicAdd(&g_cursor[d], 1);
        g_col[pos] = g_src[e];
    }
}

// ---------------- GEMM1: h1 = x @ W1 (100000x512 @ 512x64), double-buffered ----------------
#define BM 128
#define BN 64
#define BK 16
__global__ __launch_bounds__(256) void gemm1_kernel(const float* __restrict__ x,
                                                    const float* __restrict__ W) {
    __shared__ float As[2][BK][BM];   // transposed x tile
    __shared__ float Bs[2][BK][BN];
    int block_row = blockIdx.x * BM;
    int tid = threadIdx.x;          // 256
    int tx = tid & 15;              // col group (4 cols each)
    int ty = tid >> 4;              // row group (8 rows each)
    int lr = tid >> 2;              // 0..63 : x load row
    int lc = (tid & 3) * 4;         // 0,4,8,12 : x load col
    int wr = tid >> 4;              // W load row 0..15
    int wc = (tid & 15) * 4;        // W load col

    int gr0 = block_row + lr;
    int gr1 = block_row + lr + 64;
    bool ok0 = gr0 < NN, ok1 = gr1 < NN;
    const float* xp0 = x + (size_t)gr0 * FIN + lc;
    const float* xp1 = x + (size_t)gr1 * FIN + lc;
    const float* wp  = W + (size_t)wr * BN + wc;

    float acc[8][4];
    #pragma unroll
    for (int i = 0; i < 8; i++)
        #pragma unroll
        for (int j = 0; j < 4; j++) acc[i][j] = 0.f;

    const int NSTEPS = FIN / BK;    // 32
    // preload step 0 into buffer 0
    {
        float4 v0 = ok0 ? *(const float4*)xp0 : make_float4(0.f, 0.f, 0.f, 0.f);
        float4 v1 = ok1 ? *(const float4*)xp1 : make_float4(0.f, 0.f, 0.f, 0.f);
        float4 wv = *(const float4*)wp;
        As[0][lc + 0][lr] = v0.x; As[0][lc + 1][lr] = v0.y;
        As[0][lc + 2][lr] = v0.z; As[0][lc + 3][lr] = v0.w;
        As[0][lc + 0][lr + 64] = v1.x; As[0][lc + 1][lr + 64] = v1.y;
        As[0][lc + 2][lr + 64] = v1.z; As[0][lc + 3][lr + 64] = v1.w;
        Bs[0][wr][wc + 0] = wv.x; Bs[0][wr][wc + 1] = wv.y;
        Bs[0][wr][wc + 2] = wv.z; Bs[0][wr][wc + 3] = wv.w;
    }
    __syncthreads();

    for (int step = 0; step < NSTEPS; step++) {
        int cur = step & 1;
        float4 n0, n1, nw;
        bool havenext = (step + 1 < NSTEPS);
        if (havenext) {
            int k0 = (step + 1) * BK;
            n0 = ok0 ? *(const float4*)(xp0 + k0) : make_float4(0.f, 0.f, 0.f, 0.f);
            n1 = ok1 ? *(const float4*)(xp1 + k0) : make_float4(0.f, 0.f, 0.f, 0.f);
            nw = *(const float4*)(wp + (size_t)k0 * BN);
        }
        #pragma unroll
        for (int k = 0; k < BK; k++) {
            float a[8], b[4];
            #pragma unroll
            for (int i = 0; i < 8; i++) a[i] = As[cur][k][ty * 8 + i];
            #pragma unroll
            for (int j = 0; j < 4; j++) b[j] = Bs[cur][k][tx * 4 + j];
            #pragma unroll
            for (int i = 0; i < 8; i++)
                #pragma unroll
                for (int j = 0; j < 4; j++) acc[i][j] += a[i] * b[j];
        }
        if (havenext) {
            int nb = 1 - cur;
            As[nb][lc + 0][lr] = n0.x; As[nb][lc + 1][lr] = n0.y;
            As[nb][lc + 2][lr] = n0.z; As[nb][lc + 3][lr] = n0.w;
            As[nb][lc + 0][lr + 64] = n1.x; As[nb][lc + 1][lr + 64] = n1.y;
            As[nb][lc + 2][lr + 64] = n1.z; As[nb][lc + 3][lr + 64] = n1.w;
            Bs[nb][wr][wc + 0] = nw.x; Bs[nb][wr][wc + 1] = nw.y;
            Bs[nb][wr][wc + 2] = nw.z; Bs[nb][wr][wc + 3] = nw.w;
            __syncthreads();
        }
    }
    #pragma unroll
    for (int i = 0; i < 8; i++) {
        int gr = block_row + ty * 8 + i;
        if (gr < NN) {
            float4 v = make_float4(acc[i][0], acc[i][1], acc[i][2], acc[i][3]);
            *(float4*)(g_h1 + (size_t)gr * HD + tx * 4) = v;
        }
    }
}

// ---------------- attention scalars layer 1 ----------------
__global__ __launch_bounds__(256) void esed1_kernel(const float* __restrict__ a1s,
                                                    const float* __restrict__ a1d) {
    int idx = blockIdx.x * blockDim.x + threadIdx.x;
    if (idx >= NN * H1) return;
    int n = idx >> 3, h = idx & 7;
    const float* hp = g_h1 + (size_t)n * HD + h * D1;
    float s = 0.f, d = 0.f;
    #pragma unroll
    for (int j = 0; j < D1; j++) {
        float v = hp[j];
        s += v * a1s[h * D1 + j];
        d += v * a1d[h * D1 + j];
    }
    g_es1[idx] = s;
    g_ed1[idx] = d;
}

// ---------------- layer-1 aggregation: warp per dst, online softmax, ELU ----------------
__global__ __launch_bounds__(256) void agg1_kernel() {
    int warp = (blockIdx.x * blockDim.x + threadIdx.x) >> 5;
    int lane = threadIdx.x & 31;
    if (warp >= NN) return;
    int dst = warp;
    int head0 = lane >> 3;                 // head of dim d0 = lane
    float edv = (lane < 8) ? g_ed1[(size_t)dst * H1 + lane] : 0.f;
    float m = -INFINITY, s = 0.f;
    float acc0 = 0.f, acc1 = 0.f;
    int beg = g_rowptr[dst], end = g_rowptr[dst + 1];
    for (int e = beg; e < end; e++) {
        int src = g_col[e];
        float scale = 1.f, w = 0.f;
        if (lane < 8) {
            float ev = g_es1[(size_t)src * H1 + lane] + edv;
            ev = ev > 0.f ? ev : 0.2f * ev;
            float nm = fmaxf(m, ev);
            scale = __expf(m - nm);
            w = __expf(ev - nm);
            m = nm;
            s = s * scale + w;
        }
        float sc0 = __shfl_sync(0xffffffffu, scale, head0);
        float w0  = __shfl_sync(0xffffffffu, w,     head0);
        float sc1 = __shfl_sync(0xffffffffu, scale, head0 + 4);
        float w1  = __shfl_sync(0xffffffffu, w,     head0 + 4);
        float hv0 = g_h1[(size_t)src * HD + lane];
        float hv1 = g_h1[(size_t)src * HD + lane + 32];
        acc0 = acc0 * sc0 + hv0 * w0;
        acc1 = acc1 * sc1 + hv1 * w1;
    }
    float s0 = __shfl_sync(0xffffffffu, s, head0);
    float s1 = __shfl_sync(0xffffffffu, s, head0 + 4);
    float o0 = acc0 / s0;
    float o1 = acc1 / s1;
    o0 = o0 > 0.f ? o0 : expm1f(o0);       // ELU
    o1 = o1 > 0.f ? o1 : expm1f(o1);
    g_h1act[(size_t)dst * HD + lane] = o0;
    g_h1act[(size_t)dst * HD + lane + 32] = o1;
}

// ---------------- GEMM2: h2 = h1act @ W2 (64 -> 16) ----------------
__global__ __launch_bounds__(256) void gemm2_kernel(const float* __restrict__ W2) {
    __shared__ float Ws[HD * CC];
    int t = threadIdx.x;
    {
        float4 v = ((const float4*)W2)[t];   // 1024 floats = 256 float4
        ((float4*)Ws)[t] = v;
    }
    __syncthreads();
    int idx = blockIdx.x * 256 + t;
    if (idx >= NN * CC) return;
    int n = idx >> 4, c = idx & 15;
    const float4* h4 = (const float4*)(g_h1act + (size_t)n * HD);
    float sum = 0.f;
    #pragma unroll
    for (int j = 0; j < 16; j++) {
        float4 v = h4[j];
        sum += v.x * Ws[(4 * j + 0) * CC + c];
        sum += v.y * Ws[(4 * j + 1) * CC + c];
        sum += v.z * Ws[(4 * j + 2) * CC + c];
        sum += v.w * Ws[(4 * j + 3) * CC + c];
    }
    g_h2[idx] = sum;
}

__global__ __launch_bounds__(256) void esed2_kernel(const float* __restrict__ a2s,
                                                    const float* __restrict__ a2d) {
    int n = blockIdx.x * blockDim.x + threadIdx.x;
    if (n >= NN) return;
    const float4* h4 = (const float4*)(g_h2 + (size_t)n * CC);
    float s = 0.f, d = 0.f;
    #pragma unroll
    for (int j = 0; j < 4; j++) {
        float4 v = h4[j];
        s += v.x * a2s[4 * j + 0] + v.y * a2s[4 * j + 1] + v.z * a2s[4 * j + 2] + v.w * a2s[4 * j + 3];
        d += v.x * a2d[4 * j + 0] + v.y * a2d[4 * j + 1] + v.z * a2d[4 * j + 2] + v.w * a2d[4 * j + 3];
    }
    g_es2[n] = s;
    g_ed2[n] = d;
}

// ---------------- layer-2 aggregation + log_softmax : half-warp per dst ----------------
__global__ __launch_bounds__(256) void agg2_kernel(float* __restrict__ out) {
    int gw = (blockIdx.x * blockDim.x + threadIdx.x) >> 5;
    int lane = threadIdx.x & 31;
    int half = lane >> 4;
    int r = lane & 15;
    int dst = gw * 2 + half;     // NN even and grid exact -> always valid
    float edv = g_ed2[dst];
    float m = -INFINITY, s = 0.f, acc = 0.f;
    int beg = g_rowptr[dst], end = g_rowptr[dst + 1];
    for (int e = beg; e < end; e++) {
        int src = g_col[e];
        float ev = g_es2[src] + edv;
        ev = ev > 0.f ? ev : 0.2f * ev;
        float nm = fmaxf(m, ev);
        float scale = __expf(m - nm);
        float w = __expf(ev - nm);
        m = nm;
        s = s * scale + w;
        acc = acc * scale + g_h2[(size_t)src * CC + r] * w;
    }
    float o = acc / s;
    // log_softmax over 16 classes within half-warp
    float mx = o;
    #pragma unroll
    for (int off = 8; off; off >>= 1)
        mx = fmaxf(mx, __shfl_xor_sync(0xffffffffu, mx, off, 16));
    float se = __expf(o - mx);
    #pragma unroll
    for (int off = 8; off; off >>= 1)
        se += __shfl_xor_sync(0xffffffffu, se, off, 16);
    out[(size_t)dst * CC + r] = o - mx - logf(se);
}

// ---------------- launch ----------------
extern "C" void kernel_launch(void* const* d_in, const int* in_sizes, int n_in,
                              void* d_out, int out_size) {
    const float* x    = (const float*)d_in[0];
    const void*  ei   = d_in[1];
    const float* W1   = (const float*)d_in[2];
    const float* a1s  = (const float*)d_in[3];
    const float* a1d  = (const float*)d_in[4];
    const float* W2   = (const float*)d_in[5];
    const float* a2s  = (const float*)d_in[6];
    const float* a2d  = (const float*)d_in[7];
    float* out = (float*)d_out;

    init_kernel<<<(NN + 255) / 256, 256>>>((const int*)ei);
    convert_hist_kernel<<<(ET + 255) / 256, 256>>>(ei);
    scan_kernel<<<1, 512>>>();
    scatter_kernel<<<(ET + 255) / 256, 256>>>();

    gemm1_kernel<<<(NN + BM - 1) / BM, 256>>>(x, W1);
    esed1_kernel<<<(NN * H1 + 255) / 256, 256>>>(a1s, a1d);
    agg1_kernel<<<(NN * 32 + 255) / 256, 256>>>();

    gemm2_kernel<<<(NN * CC + 255) / 256, 256>>>(W2);
    esed2_kernel<<<(NN + 255) / 256, 256>>>(a2s, a2d);
    agg2_kernel<<<(NN * 16 + 255) / 256, 256>>>(out);
}

// round 5
// speedup vs baseline: 1.5388x; 1.0129x over previous
#include <cuda_runtime.h>
#include <cuda_bf16.h>
#include <math.h>
#include <stdint.h>

#define NN   100000
#define EE   1600000
#define ET   1700000      // EE + NN self loops
#define FIN  512
#define HD   64           // H1*D1
#define H1   8
#define D1   8
#define CC   16

// ---------------- scratch (static device memory; no allocations) ----------------
__device__ int   g_flag;                 // 1 if edge_index is int64
__device__ int   g_src[ET];
__device__ int   g_dst[ET];
__device__ int   g_col[ET];              // CSR column (src) sorted by dst
__device__ int   g_counts[NN];
__device__ int   g_cursor[NN];
__device__ int   g_rowptr[NN + 1];
__device__ float g_h1[(size_t)NN * HD];
__device__ float g_h1act[(size_t)NN * HD];
__device__ float g_es1[(size_t)NN * H1];
__device__ float g_ed1[(size_t)NN * H1];
__device__ float g_h2[(size_t)NN * CC];
__device__ float g_es2[NN];
__device__ float g_ed2[NN];

// ---------------- init: zero counts + parallel dtype detection ----------------
__global__ __launch_bounds__(256) void init_kernel(const int* ei32) {
    int i = blockIdx.x * blockDim.x + threadIdx.x;
    if (i < NN) g_counts[i] = 0;
    if (blockIdx.x == 0 && threadIdx.x < 32) {
        int lane = threadIdx.x;
        int bad = 0;
        for (int j = lane; j < 256; j += 32) {
            int k = j * 6250;
            if (ei32[2 * k + 1] != 0) bad = 1;
        }
        unsigned b = __ballot_sync(0xffffffffu, bad);
        if (lane == 0) g_flag = (b == 0) ? 1 : 0;
    }
}

// ---------------- convert + histogram in one edge pass ----------------
__global__ __launch_bounds__(256) void convert_hist_kernel(const void* ei) {
    int e = blockIdx.x * blockDim.x + threadIdx.x;
    if (e >= ET) return;
    int s, d;
    if (e < EE) {
        if (g_flag) {
            const long long* p = (const long long*)ei;
            s = (int)p[e]; d = (int)p[EE + e];
        } else {
            const int* p = (const int*)ei;
            s = p[e]; d = p[EE + e];
        }
    } else {
        s = e - EE; d = e - EE;
    }
    g_src[e] = s; g_dst[e] = d;
    atomicAdd(&g_counts[d], 1);
}

// ---------------- scan: rowptr + cursor ----------------
__global__ __launch_bounds__(512) void scan_kernel() {
    __shared__ int sums[512];
    int t = threadIdx.x;
    const int CH = (NN + 511) / 512;
    int base = t * CH;
    int s = 0;
    for (int i = 0; i < CH; i++) {
        int idx = base + i;
        if (idx < NN) s += g_counts[idx];
    }
    sums[t] = s;
    __syncthreads();
    for (int off = 1; off < 512; off <<= 1) {
        int v = (t >= off) ? sums[t - off] : 0;
        __syncthreads();
        sums[t] += v;
        __syncthreads();
    }
    int run = (t == 0) ? 0 : sums[t - 1];
    for (int i = 0; i < CH; i++) {
        int idx = base + i;
        if (idx < NN) {
            g_rowptr[idx] = run;
            g_cursor[idx] = run;
            run += g_counts[idx];
        }
    }
    if (t == 0) g_rowptr[NN] = ET;
}

__global__ __launch_bounds__(256) void scatter_kernel() {
    int e = blockIdx.x * blockDim.x + threadIdx.x;
    if (e < ET) {
        int d = g_dst[e];
        int pos = atomicAdd(&g_cursor[d], 1);
        g_col[pos] = g_src[e];
    }
}

// ---------------- GEMM1 via mma.sync split-bf16 + fused es/ed ----------------
// CTA: 128 rows x 64 cols. 8 warps, each 32x32 (2 m-tiles x 4 n-tiles of m16n8k16).
// D = Ah*Bh + Al*Bh + Ah*Bl, fp32 accumulate.
#define KC 256           // K chunk held in smem (W transposed bf16 hi/lo)
#define ST 264           // padded k-stride (bank-conflict-free B loads)
#define G1_SMEM (2 * 64 * ST * 2)   // hi + lo, bf16

__device__ __forceinline__ void cvt_pair(float vx, float vy, uint32_t& hi, uint32_t& lo) {
    asm("cvt.rn.bf16x2.f32 %0, %1, %2;" : "=r"(hi) : "f"(vy), "f"(vx));
    float h0 = __uint_as_float(hi << 16);
    float h1 = __uint_as_float(hi & 0xFFFF0000u);
    float r0 = vx - h0, r1 = vy - h1;
    asm("cvt.rn.bf16x2.f32 %0, %1, %2;" : "=r"(lo) : "f"(r1), "f"(r0));
}

__device__ __forceinline__ void mma16816(float* c, const uint32_t* a, uint32_t b0, uint32_t b1) {
    asm volatile(
        "mma.sync.aligned.m16n8k16.row.col.f32.bf16.bf16.f32 "
        "{%0,%1,%2,%3}, {%4,%5,%6,%7}, {%8,%9}, {%0,%1,%2,%3};"
        : "+f"(c[0]), "+f"(c[1]), "+f"(c[2]), "+f"(c[3])
        : "r"(a[0]), "r"(a[1]), "r"(a[2]), "r"(a[3]), "r"(b0), "r"(b1));
}

__global__ __launch_bounds__(256, 2) void gemm1_mma_kernel(const float* __restrict__ x,
                                                           const float* __restrict__ W,
                                                           const float* __restrict__ a1s,
                                                           const float* __restrict__ a1d) {
    extern __shared__ __nv_bfloat16 ws[];
    __nv_bfloat16* whi = ws;                 // [64][ST]
    __nv_bfloat16* wlo = ws + 64 * ST;       // [64][ST]
    int tid = threadIdx.x;
    int wid = tid >> 5, lane = tid & 31;
    int g = lane >> 2, tc = lane & 3;
    int wm = wid & 3, wn = wid >> 2;
    int row_base = blockIdx.x * 128 + wm * 32;

    float acc[2][4][4];
    #pragma unroll
    for (int mt = 0; mt < 2; mt++)
        #pragma unroll
        for (int nt = 0; nt < 4; nt++)
            #pragma unroll
            for (int q = 0; q < 4; q++) acc[mt][nt][q] = 0.f;

    for (int ch = 0; ch < 2; ch++) {
        int kb = ch * KC;
        // ---- load & convert W chunk (transposed, hi/lo) ----
        for (int i = tid; i < 64 * KC; i += 256) {
            int kk = i >> 6;                  // 0..KC-1
            int n = i & 63;
            float v = W[(size_t)(kb + kk) * HD + n];
            __nv_bfloat16 h = __float2bfloat16_rn(v);
            float r = v - __bfloat162float(h);
            whi[n * ST + kk] = h;
            wlo[n * ST + kk] = __float2bfloat16_rn(r);
        }
        __syncthreads();

        for (int ks = 0; ks < KC / 16; ks++) {
            int k0 = kb + ks * 16;
            // ---- A fragments from global, convert to hi/lo ----
            uint32_t ah[2][4], al[2][4];
            #pragma unroll
            for (int mt = 0; mt < 2; mt++) {
                int r0 = row_base + mt * 16 + g;
                int r1 = r0 + 8;
                const float* p0 = x + (size_t)r0 * FIN + k0 + tc * 2;
                const float* p1 = x + (size_t)r1 * FIN + k0 + tc * 2;
                float2 z = make_float2(0.f, 0.f);
                float2 v0 = (r0 < NN) ? *(const float2*)p0 : z;
                float2 v1 = (r1 < NN) ? *(const float2*)p1 : z;
                float2 v2 = (r0 < NN) ? *(const float2*)(p0 + 8) : z;
                float2 v3 = (r1 < NN) ? *(const float2*)(p1 + 8) : z;
                cvt_pair(v0.x, v0.y, ah[mt][0], al[mt][0]);
                cvt_pair(v1.x, v1.y, ah[mt][1], al[mt][1]);
                cvt_pair(v2.x, v2.y, ah[mt][2], al[mt][2]);
                cvt_pair(v3.x, v3.y, ah[mt][3], al[mt][3]);
            }
            // ---- B fragments from smem + MMAs ----
            int kl = ks * 16 + tc * 2;
            #pragma unroll
            for (int nt = 0; nt < 4; nt++) {
                int n = wn * 32 + nt * 8 + g;
                const __nv_bfloat16* ph = whi + n * ST + kl;
                const __nv_bfloat16* pl = wlo + n * ST + kl;
                uint32_t bh0 = *(const uint32_t*)ph;
                uint32_t bh1 = *(const uint32_t*)(ph + 8);
                uint32_t bl0 = *(const uint32_t*)pl;
                uint32_t bl1 = *(const uint32_t*)(pl + 8);
                #pragma unroll
                for (int mt = 0; mt < 2; mt++) {
                    mma16816(acc[mt][nt], ah[mt], bh0, bh1);
                    mma16816(acc[mt][nt], al[mt], bh0, bh1);
                    mma16816(acc[mt][nt], ah[mt], bl0, bl1);
                }
            }
        }
        __syncthreads();   // protect smem before next chunk overwrite
    }

    // ---- epilogue: write h1, fused es/ed ----
    int col_base = wn * 32;
    #pragma unroll
    for (int mt = 0; mt < 2; mt++) {
        int r0 = row_base + mt * 16 + g;
        int r1 = r0 + 8;
        #pragma unroll
        for (int nt = 0; nt < 4; nt++) {
            int col = col_base + nt * 8 + tc * 2;
            float* c = acc[mt][nt];
            if (r0 < NN) *(float2*)(g_h1 + (size_t)r0 * HD + col) = make_float2(c[0], c[1]);
            if (r1 < NN) *(float2*)(g_h1 + (size_t)r1 * HD + col) = make_float2(c[2], c[3]);
            int head = (col_base >> 3) + nt;
            float as0 = a1s[head * 8 + tc * 2], as1 = a1s[head * 8 + tc * 2 + 1];
            float ad0 = a1d[head * 8 + tc * 2], ad1 = a1d[head * 8 + tc * 2 + 1];
            float es_a = c[0] * as0 + c[1] * as1;
            float ed_a = c[0] * ad0 + c[1] * ad1;
            float es_b = c[2] * as0 + c[3] * as1;
            float ed_b = c[2] * ad0 + c[3] * ad1;
            es_a += __shfl_xor_sync(0xffffffffu, es_a, 1); es_a += __shfl_xor_sync(0xffffffffu, es_a, 2);
            ed_a += __shfl_xor_sync(0xffffffffu, ed_a, 1); ed_a += __shfl_xor_sync(0xffffffffu, ed_a, 2);
            es_b += __shfl_xor_sync(0xffffffffu, es_b, 1); es_b += __shfl_xor_sync(0xffffffffu, es_b, 2);
            ed_b += __shfl_xor_sync(0xffffffffu, ed_b, 1); ed_b += __shfl_xor_sync(0xffffffffu, ed_b, 2);
            if (tc == 0) {
                if (r0 < NN) { g_es1[(size_t)r0 * H1 + head] = es_a; g_ed1[(size_t)r0 * H1 + head] = ed_a; }
                if (r1 < NN) { g_es1[(size_t)r1 * H1 + head] = es_b; g_ed1[(size_t)r1 * H1 + head] = ed_b; }
            }
        }
    }
}

// ---------------- layer-1 aggregation: warp per dst, online softmax, ELU ----------------
__global__ __launch_bounds__(256) void agg1_kernel() {
    int warp = (blockIdx.x * blockDim.x + threadIdx.x) >> 5;
    int lane = threadIdx.x & 31;
    if (warp >= NN) return;
    int dst = warp;
    int head0 = lane >> 3;
    float edv = (lane < 8) ? g_ed1[(size_t)dst * H1 + lane] : 0.f;
    float m = -INFINITY, s = 0.f;
    float acc0 = 0.f, acc1 = 0.f;
    int beg = g_rowptr[dst], end = g_rowptr[dst + 1];
    for (int e = beg; e < end; e++) {
        int src = g_col[e];
        float scale = 1.f, w = 0.f;
        if (lane < 8) {
            float ev = g_es1[(size_t)src * H1 + lane] + edv;
            ev = ev > 0.f ? ev : 0.2f * ev;
            float nm = fmaxf(m, ev);
            scale = __expf(m - nm);
            w = __expf(ev - nm);
            m = nm;
            s = s * scale + w;
        }
        float sc0 = __shfl_sync(0xffffffffu, scale, head0);
        float w0  = __shfl_sync(0xffffffffu, w,     head0);
        float sc1 = __shfl_sync(0xffffffffu, scale, head0 + 4);
        float w1  = __shfl_sync(0xffffffffu, w,     head0 + 4);
        float hv0 = g_h1[(size_t)src * HD + lane];
        float hv1 = g_h1[(size_t)src * HD + lane + 32];
        acc0 = acc0 * sc0 + hv0 * w0;
        acc1 = acc1 * sc1 + hv1 * w1;
    }
    float s0 = __shfl_sync(0xffffffffu, s, head0);
    float s1 = __shfl_sync(0xffffffffu, s, head0 + 4);
    float o0 = acc0 / s0;
    float o1 = acc1 / s1;
    o0 = o0 > 0.f ? o0 : expm1f(o0);
    o1 = o1 > 0.f ? o1 : expm1f(o1);
    g_h1act[(size_t)dst * HD + lane] = o0;
    g_h1act[(size_t)dst * HD + lane + 32] = o1;
}

// ---------------- GEMM2: h2 = h1act @ W2 (64 -> 16) ----------------
__global__ __launch_bounds__(256) void gemm2_kernel(const float* __restrict__ W2) {
    __shared__ float Ws[HD * CC];
    int t = threadIdx.x;
    {
        float4 v = ((const float4*)W2)[t];
        ((float4*)Ws)[t] = v;
    }
    __syncthreads();
    int idx = blockIdx.x * 256 + t;
    if (idx >= NN * CC) return;
    int n = idx >> 4, c = idx & 15;
    const float4* h4 = (const float4*)(g_h1act + (size_t)n * HD);
    float sum = 0.f;
    #pragma unroll
    for (int j = 0; j < 16; j++) {
        float4 v = h4[j];
        sum += v.x * Ws[(4 * j + 0) * CC + c];
        sum += v.y * Ws[(4 * j + 1) * CC + c];
        sum += v.z * Ws[(4 * j + 2) * CC + c];
        sum += v.w * Ws[(4 * j + 3) * CC + c];
    }
    g_h2[idx] = sum;
}

__global__ __launch_bounds__(256) void esed2_kernel(const float* __restrict__ a2s,
                                                    const float* __restrict__ a2d) {
    int n = blockIdx.x * blockDim.x + threadIdx.x;
    if (n >= NN) return;
    const float4* h4 = (const float4*)(g_h2 + (size_t)n * CC);
    float s = 0.f, d = 0.f;
    #pragma unroll
    for (int j = 0; j < 4; j++) {
        float4 v = h4[j];
        s += v.x * a2s[4 * j + 0] + v.y * a2s[4 * j + 1] + v.z * a2s[4 * j + 2] + v.w * a2s[4 * j + 3];
        d += v.x * a2d[4 * j + 0] + v.y * a2d[4 * j + 1] + v.z * a2d[4 * j + 2] + v.w * a2d[4 * j + 3];
    }
    g_es2[n] = s;
    g_ed2[n] = d;
}

// ---------------- layer-2 aggregation + log_softmax : half-warp per dst ----------------
__global__ __launch_bounds__(256) void agg2_kernel(float* __restrict__ out) {
    int gw = (blockIdx.x * blockDim.x + threadIdx.x) >> 5;
    int lane = threadIdx.x & 31;
    int half = lane >> 4;
    int r = lane & 15;
    int dst = gw * 2 + half;
    float edv = g_ed2[dst];
    float m = -INFINITY, s = 0.f, acc = 0.f;
    int beg = g_rowptr[dst], end = g_rowptr[dst + 1];
    for (int e = beg; e < end; e++) {
        int src = g_col[e];
        float ev = g_es2[src] + edv;
        ev = ev > 0.f ? ev : 0.2f * ev;
        float nm = fmaxf(m, ev);
        float scale = __expf(m - nm);
        float w = __expf(ev - nm);
        m = nm;
        s = s * scale + w;
        acc = acc * scale + g_h2[(size_t)src * CC + r] * w;
    }
    float o = acc / s;
    float mx = o;
    #pragma unroll
    for (int off = 8; off; off >>= 1)
        mx = fmaxf(mx, __shfl_xor_sync(0xffffffffu, mx, off, 16));
    float se = __expf(o - mx);
    #pragma unroll
    for (int off = 8; off; off >>= 1)
        se += __shfl_xor_sync(0xffffffffu, se, off, 16);
    out[(size_t)dst * CC + r] = o - mx - logf(se);
}

// ---------------- launch ----------------
extern "C" void kernel_launch(void* const* d_in, const int* in_sizes, int n_in,
                              void* d_out, int out_size) {
    const float* x    = (const float*)d_in[0];
    const void*  ei   = d_in[1];
    const float* W1   = (const float*)d_in[2];
    const float* a1s  = (const float*)d_in[3];
    const float* a1d  = (const float*)d_in[4];
    const float* W2   = (const float*)d_in[5];
    const float* a2s  = (const float*)d_in[6];
    const float* a2d  = (const float*)d_in[7];
    float* out = (float*)d_out;

    cudaFuncSetAttribute(gemm1_mma_kernel, cudaFuncAttributeMaxDynamicSharedMemorySize, G1_SMEM);

    init_kernel<<<(NN + 255) / 256, 256>>>((const int*)ei);
    convert_hist_kernel<<<(ET + 255) / 256, 256>>>(ei);
    scan_kernel<<<1, 512>>>();
    scatter_kernel<<<(ET + 255) / 256, 256>>>();

    gemm1_mma_kernel<<<(NN + 127) / 128, 256, G1_SMEM>>>(x, W1, a1s, a1d);
    agg1_kernel<<<(NN * 32 + 255) / 256, 256>>>();

    gemm2_kernel<<<(NN * CC + 255) / 256, 256>>>(W2);
    esed2_kernel<<<(NN + 255) / 256, 256>>>(a2s, a2d);
    agg2_kernel<<<(NN * 16 + 255) / 256, 256>>>(out);
}